// round 6
// baseline (speedup 1.0000x reference)
#include <cuda_runtime.h>
#include <math.h>

#define BATCH 64
#define CH 512
#define WD 512
#define NPIX 16
#define NCOL (CH*NPIX)   /* 8192 */
#define KC 64            /* k-tile */
#define TN 64            /* n-tile = 4 out-ch x 16 px */

// ---- scratch (allocation-free rule: __device__ globals) ----
__device__ __align__(16) float g_sT[CH*BATCH];   // style transposed [i][b]
__device__ __align__(16) float g_s2[BATCH*CH];   // style^2, b-major [b][i]

union F2 { float2 f; unsigned long long u; };
__device__ __forceinline__ void fma2(F2& d, F2 a, F2 b) {
    asm("fma.rn.f32x2 %0, %1, %2, %0;" : "+l"(d.u) : "l"(a.u), "l"(b.u));
}

// ---------------- Kernel A: style dense  s = w0 @ (mod_w/sqrt(512)) + mod_b + 1
__global__ __launch_bounds__(256) void style_kernel(
        const float* __restrict__ w0,
        const float* __restrict__ mod_w,
        const float* __restrict__ mod_b) {
    __shared__ float w0s[64][68];
    __shared__ float mwsT[8][68];
    const int tid = threadIdx.x;
    const int c  = tid & 7;
    const int bg = tid >> 3;         // 0..31 (2 b each)
    const int c0 = blockIdx.x * 8;

    float acc0 = 0.f, acc1 = 0.f;

    for (int jt = 0; jt < 8; jt++) {
        #pragma unroll
        for (int q = 0; q < 4; q++) {
            int f = tid + q*256;
            int b = f >> 4, jq = f & 15;
            *(float4*)&w0s[b][jq*4] =
                *(const float4*)&w0[b*WD + jt*64 + jq*4];
        }
        if (tid < 128) {
            int j = tid >> 1, cq = tid & 1;
            float4 v = *(const float4*)&mod_w[(size_t)(jt*64 + j)*CH + c0 + cq*4];
            mwsT[cq*4 + 0][j] = v.x;
            mwsT[cq*4 + 1][j] = v.y;
            mwsT[cq*4 + 2][j] = v.z;
            mwsT[cq*4 + 3][j] = v.w;
        }
        __syncthreads();
        #pragma unroll
        for (int j4 = 0; j4 < 16; j4++) {
            float4 mv = *(const float4*)&mwsT[c][j4*4];
            float4 a0 = *(const float4*)&w0s[bg*2    ][j4*4];
            float4 a1 = *(const float4*)&w0s[bg*2 + 1][j4*4];
            acc0 += a0.x*mv.x + a0.y*mv.y + a0.z*mv.z + a0.w*mv.w;
            acc1 += a1.x*mv.x + a1.y*mv.y + a1.z*mv.z + a1.w*mv.w;
        }
        __syncthreads();
    }
    const float inv = 1.0f / sqrtf((float)WD);
    float bb = mod_b[c0 + c] + 1.0f;
    float s0 = acc0*inv + bb;
    float s1 = acc1*inv + bb;
    int ch = c0 + c;
    g_sT[(size_t)ch*BATCH + bg*2    ] = s0;
    g_sT[(size_t)ch*BATCH + bg*2 + 1] = s1;
    g_s2[(size_t)(bg*2    )*CH + ch] = s0*s0;
    g_s2[(size_t)(bg*2 + 1)*CH + ch] = s1*s1;
}

// ---------------- Kernel B: fused modconv, double-buffered, 1 barrier/tile
// grid 128 (one n-tile, full M=64), 256 threads, thread tile 4m x 4n (f32x2 m-pairs).
struct Smem {
    float s_s[2][KC][BATCH];     // 32KB
    float u_s[2][KC][TN + 4];    // 34KB
    float q_T[4][CH + 8];        // 8.3KB  q transposed [og][k]
    float d_s[4][BATCH];         // 1KB
};
#define SMEM_BYTES ((int)sizeof(Smem))

__global__ __launch_bounds__(256) void fused_kernel(
        const float* __restrict__ conv_w,    // [3,3,512,512] HWIO
        const float* __restrict__ cst,       // [1,512,4,4]
        const float* __restrict__ noise,     // [B,1,4,4]
        const float* __restrict__ ns_ptr,    // scalar
        const float* __restrict__ bias,      // [C]
        float* __restrict__ out) {           // [B,C,4,4]
    extern __shared__ char smem_raw[];
    Smem* sm = (Smem*)smem_raw;

    const int tid = threadIdx.x;
    const int tx = tid & 15;                 // 4 n each
    const int ty = tid >> 4;                 // 0..15, 4 m each
    const int n0 = blockIdx.x * TN;
    const int o0 = n0 >> 4;

    const int bi = tid >> 2;                 // U-build input channel (local)
    const int bo = tid & 3;                  // U-build output channel (local)

    const float coef = 1.0f / sqrtf(9.0f * (float)CH);

    F2 acc[2][4];
    #pragma unroll
    for (int a = 0; a < 2; a++)
        #pragma unroll
        for (int c = 0; c < 4; c++) { acc[a][c].f.x = 0.f; acc[a][c].f.y = 0.f; }

    // ---- prefetch registers (one k-tile ahead) ----
    float  w9[9];
    float4 c4[4];
    float4 s4[4];
    const float* wp = conv_w + (size_t)bi*CH + o0 + bo;
    const float4* cp = (const float4*)&cst[bi*NPIX];

    // load tile 0
    #pragma unroll
    for (int t = 0; t < 9; t++) w9[t] = wp[(size_t)t*CH*CH];
    #pragma unroll
    for (int qd = 0; qd < 4; qd++) c4[qd] = cp[qd];
    #pragma unroll
    for (int j = 0; j < 4; j++) {
        int f = tid + j*256;
        int k = f >> 4, mq = f & 15;
        s4[j] = *(const float4*)&g_sT[(size_t)k*BATCH + mq*4];
    }

    // store tile 0 into buffer 0
    {
        // s stage
        #pragma unroll
        for (int j = 0; j < 4; j++) {
            int f = tid + j*256;
            int k = f >> 4, mq = f & 15;
            *(float4*)&sm->s_s[0][k][mq*4] = s4[j];
        }
        // U build + q
        float q = 0.f, wr[9];
        #pragma unroll
        for (int t = 0; t < 9; t++) { float w = w9[t]*coef; wr[t] = w; q += w*w; }
        sm->q_T[bo][bi] = q;
        float c16[NPIX];
        *(float4*)&c16[0] = c4[0]; *(float4*)&c16[4] = c4[1];
        *(float4*)&c16[8] = c4[2]; *(float4*)&c16[12] = c4[3];
        #pragma unroll
        for (int h = 0; h < 4; h++) {
            float u4[4];
            #pragma unroll
            for (int x = 0; x < 4; x++) {
                float a = 0.f;
                #pragma unroll
                for (int kh = 0; kh < 3; kh++) {
                    int hh = h + kh - 1;
                    if (hh < 0 || hh >= 4) continue;
                    #pragma unroll
                    for (int kw = 0; kw < 3; kw++) {
                        int xx = x + kw - 1;
                        if (xx < 0 || xx >= 4) continue;
                        a += wr[kh*3 + kw] * c16[hh*4 + xx];
                    }
                }
                u4[x] = a;
            }
            *(float4*)&sm->u_s[0][bi][bo*NPIX + h*4] = *(float4*)&u4[0];
        }
    }
    __syncthreads();

    for (int kt = 0; kt < 8; kt++) {
        const int cur = kt & 1;
        // ---- prefetch next tile's regs (LDGs land during GEMM) ----
        if (kt < 7) {
            const int kn = (kt + 1) * KC;
            const float* wpn = wp + (size_t)kn*CH;
            #pragma unroll
            for (int t = 0; t < 9; t++) w9[t] = wpn[(size_t)t*CH*CH];
            const float4* cpn = cp + kn*(NPIX/4);
            #pragma unroll
            for (int qd = 0; qd < 4; qd++) c4[qd] = cpn[qd];
            #pragma unroll
            for (int j = 0; j < 4; j++) {
                int f = tid + j*256;
                int k = f >> 4, mq = f & 15;
                s4[j] = *(const float4*)&g_sT[(size_t)(kn + k)*BATCH + mq*4];
            }
        }

        // ---- GEMM on current buffer: 4m x 4n, m packed f32x2 ----
        #pragma unroll 4
        for (int k = 0; k < KC; k++) {
            float4 sa = *(const float4*)&sm->s_s[cur][k][ty*4];
            float4 uv = *(const float4*)&sm->u_s[cur][k][tx*4];
            F2 p0, p1, u0, u1, u2, u3;
            p0.f = make_float2(sa.x, sa.y);
            p1.f = make_float2(sa.z, sa.w);
            u0.f = make_float2(uv.x, uv.x);
            u1.f = make_float2(uv.y, uv.y);
            u2.f = make_float2(uv.z, uv.z);
            u3.f = make_float2(uv.w, uv.w);
            fma2(acc[0][0], p0, u0); fma2(acc[0][1], p0, u1);
            fma2(acc[0][2], p0, u2); fma2(acc[0][3], p0, u3);
            fma2(acc[1][0], p1, u0); fma2(acc[1][1], p1, u1);
            fma2(acc[1][2], p1, u2); fma2(acc[1][3], p1, u3);
        }

        // ---- store next tile into other buffer ----
        if (kt < 7) {
            const int nxt = cur ^ 1;
            const int kn = (kt + 1) * KC;
            #pragma unroll
            for (int j = 0; j < 4; j++) {
                int f = tid + j*256;
                int k = f >> 4, mq = f & 15;
                *(float4*)&sm->s_s[nxt][k][mq*4] = s4[j];
            }
            float q = 0.f, wr[9];
            #pragma unroll
            for (int t = 0; t < 9; t++) { float w = w9[t]*coef; wr[t] = w; q += w*w; }
            sm->q_T[bo][kn + bi] = q;
            float c16[NPIX];
            *(float4*)&c16[0] = c4[0]; *(float4*)&c16[4] = c4[1];
            *(float4*)&c16[8] = c4[2]; *(float4*)&c16[12] = c4[3];
            #pragma unroll
            for (int h = 0; h < 4; h++) {
                float u4[4];
                #pragma unroll
                for (int x = 0; x < 4; x++) {
                    float a = 0.f;
                    #pragma unroll
                    for (int kh = 0; kh < 3; kh++) {
                        int hh = h + kh - 1;
                        if (hh < 0 || hh >= 4) continue;
                        #pragma unroll
                        for (int kw = 0; kw < 3; kw++) {
                            int xx = x + kw - 1;
                            if (xx < 0 || xx >= 4) continue;
                            a += wr[kh*3 + kw] * c16[hh*4 + xx];
                        }
                    }
                    u4[x] = a;
                }
                *(float4*)&sm->u_s[nxt][bi][bo*NPIX + h*4] = *(float4*)&u4[0];
            }
        }
        __syncthreads();
    }

    // ---- deferred demod: one (m, og) per thread, full k=512 ----
    {
        const int dm = tid & 63;
        const int dg = tid >> 6;
        float a2 = 1e-8f;
        const float4* sp = (const float4*)&g_s2[(size_t)dm*CH];
        #pragma unroll 4
        for (int k4 = 0; k4 < CH/4; k4++) {
            float4 s2v = sp[k4];
            float4 qv  = *(const float4*)&sm->q_T[dg][k4*4];
            a2 = fmaf(s2v.x, qv.x, a2);
            a2 = fmaf(s2v.y, qv.y, a2);
            a2 = fmaf(s2v.z, qv.z, a2);
            a2 = fmaf(s2v.w, qv.w, a2);
        }
        sm->d_s[dg][dm] = rsqrtf(a2);
    }
    __syncthreads();

    // ---- epilogue ----
    const float nstr = ns_ptr[0];
    const int og = tx >> 2;
    const float bb = bias[o0 + og];
    const int px = (tx & 3) * 4;
    const float gain = 1.41421356237309515f;
    #pragma unroll
    for (int a = 0; a < 4; a++) {
        int b = ty*4 + a;
        float dv = sm->d_s[og][b];
        float4 nz = *(const float4*)&noise[b*NPIX + px];
        float v[4];
        #pragma unroll
        for (int c = 0; c < 4; c++) {
            float x = ((a & 1) ? acc[a>>1][c].f.y : acc[a>>1][c].f.x) * dv;
            float nv = (c==0?nz.x:c==1?nz.y:c==2?nz.z:nz.w);
            x = x + nv*nstr + bb;
            x = (x > 0.f ? x : 0.2f*x) * gain;
            v[c] = x;
        }
        *(float4*)&out[(size_t)b*NCOL + n0 + tx*4] =
            make_float4(v[0], v[1], v[2], v[3]);
    }
}

extern "C" void kernel_launch(void* const* d_in, const int* in_sizes, int n_in,
                              void* d_out, int out_size) {
    const float* w0     = (const float*)d_in[0];
    const float* cst    = (const float*)d_in[1];
    const float* conv_w = (const float*)d_in[2];
    const float* mod_w  = (const float*)d_in[3];
    const float* mod_b  = (const float*)d_in[4];
    const float* noise  = (const float*)d_in[5];
    const float* nstr   = (const float*)d_in[6];
    const float* bias   = (const float*)d_in[7];
    float* out = (float*)d_out;

    cudaFuncSetAttribute(fused_kernel,
        cudaFuncAttributeMaxDynamicSharedMemorySize, SMEM_BYTES);

    style_kernel<<<64, 256>>>(w0, mod_w, mod_b);
    fused_kernel<<<NCOL / TN, 256, SMEM_BYTES>>>(conv_w, cst, noise, nstr, bias, out);
}